// round 3
// baseline (speedup 1.0000x reference)
#include <cuda_runtime.h>
#include <math.h>

// EyesMouthLoss: mean(|pred-target| * (1 + priority*299))
// priority(b,y,x) = clip(eye + mouth, 0, 1), each region =
//   max over its landmarks of clip(1 - dist/15, 0, 1)
//
// Algebra: max_j clip(1 - d_j/R) == clip(1 - sqrt(min_j d_j^2)/R)  (2 sqrts/pixel)
// Pruning: landmark only touches rows with (y-cy)^2 < R^2 (~2 active/row on avg)
// Single kernel: unconditional partial stores + last-block-done final reduce
// (no init kernel, no fin kernel, counter self-resets for graph replay).

#define H 512
#define W 512
#define C 3
#define B 16
#define NBLK (B * H)          // 8192
#define RADIUS2 225.0f
#define INV_R (1.0f / 15.0f)
#define N_TOTAL ((double)B * C * H * W)

__device__ float g_partials[NBLK];
__device__ unsigned int g_count;   // zero-initialized at load; last block resets it

__global__ void __launch_bounds__(128) eml_fused(
    const float* __restrict__ pred,
    const float* __restrict__ target,
    const int*   __restrict__ lm,
    float* __restrict__ out)
{
    // one block per (batch, row)
    const int row = blockIdx.x;          // b*H + y
    const int b   = row >> 9;
    const int y   = row & (H - 1);
    const int tid = threadIdx.x;

    __shared__ float s_ecx[12], s_ed2[12];
    __shared__ float s_mcx[20], s_md2[20];
    __shared__ int   s_ne, s_nm;
    __shared__ float s_part[4];
    __shared__ bool  s_last;

    if (tid == 0) { s_ne = 0; s_nm = 0; }
    __syncthreads();

    // prescan: threads 36..67 each own one landmark; keep row-active ones
    if (tid >= 36 && tid < 68) {
        const int lx = lm[b * 136 + tid * 2 + 0];
        const int ly = lm[b * 136 + tid * 2 + 1];
        const float cx = fminf(fmaxf((float)lx, 0.0f), (float)(W - 1));
        const float cy = fminf(fmaxf((float)ly, 0.0f), (float)(H - 1));
        const float dy  = (float)y - cy;
        const float dy2 = dy * dy;
        if (dy2 < RADIUS2) {
            if (tid < 48) { int k = atomicAdd(&s_ne, 1); s_ecx[k] = cx; s_ed2[k] = dy2; }
            else          { int k = atomicAdd(&s_nm, 1); s_mcx[k] = cx; s_md2[k] = dy2; }
        }
    }
    __syncthreads();

    const int ne = s_ne;
    const int nm = s_nm;

    // each thread: 4 consecutive pixels (float4) x 3 channels
    const int x0 = tid << 2;

    float wgt[4];
#pragma unroll
    for (int k = 0; k < 4; k++) {
        const float xf = (float)(x0 + k);
        float emn = 3.0e8f, mmn = 3.0e8f;
        for (int j = 0; j < ne; j++) {
            const float dx = xf - s_ecx[j];
            emn = fminf(emn, fmaf(dx, dx, s_ed2[j]));
        }
        for (int j = 0; j < nm; j++) {
            const float dx = xf - s_mcx[j];
            mmn = fminf(mmn, fmaf(dx, dx, s_md2[j]));
        }
        const float e = (emn < RADIUS2) ? (1.0f - sqrtf(emn) * INV_R) : 0.0f;
        const float m = (mmn < RADIUS2) ? (1.0f - sqrtf(mmn) * INV_R) : 0.0f;
        const float p = fminf(e + m, 1.0f);
        wgt[k] = fmaf(p, 299.0f, 1.0f);
    }

    const size_t rowbase = (size_t)b * (C * H * W) + (size_t)y * W + x0;
    float acc = 0.0f;
#pragma unroll
    for (int c = 0; c < C; c++) {
        const size_t off = rowbase + (size_t)c * (H * W);
        const float4 pv = *reinterpret_cast<const float4*>(pred + off);
        const float4 tv = *reinterpret_cast<const float4*>(target + off);
        acc = fmaf(fabsf(pv.x - tv.x), wgt[0], acc);
        acc = fmaf(fabsf(pv.y - tv.y), wgt[1], acc);
        acc = fmaf(fabsf(pv.z - tv.z), wgt[2], acc);
        acc = fmaf(fabsf(pv.w - tv.w), wgt[3], acc);
    }

    // warp reduce (float; block sum ~2e3, fp32 ok)
#pragma unroll
    for (int s = 16; s > 0; s >>= 1)
        acc += __shfl_xor_sync(0xFFFFFFFFu, acc, s);

    if ((tid & 31) == 0) s_part[tid >> 5] = acc;
    __syncthreads();

    if (tid == 0) {
        g_partials[row] = s_part[0] + s_part[1] + s_part[2] + s_part[3];
        __threadfence();
        unsigned int ticket = atomicAdd(&g_count, 1u);
        s_last = (ticket == (unsigned int)(NBLK - 1));
    }
    __syncthreads();

    if (s_last) {
        // last block: reduce all 8192 partials in double
        double dsum = 0.0;
        for (int i = tid; i < NBLK; i += 128)
            dsum += (double)g_partials[i];
#pragma unroll
        for (int s = 16; s > 0; s >>= 1)
            dsum += __shfl_xor_sync(0xFFFFFFFFu, dsum, s);

        __shared__ double s_dpart[4];
        if ((tid & 31) == 0) s_dpart[tid >> 5] = dsum;
        __syncthreads();

        if (tid == 0) {
            const double total = s_dpart[0] + s_dpart[1] + s_dpart[2] + s_dpart[3];
            out[0] = (float)(total / N_TOTAL);
            g_count = 0;   // reset for next graph replay (deterministic)
        }
    }
}

extern "C" void kernel_launch(void* const* d_in, const int* in_sizes, int n_in,
                              void* d_out, int out_size)
{
    const float* pred   = (const float*)d_in[0];
    const float* target = (const float*)d_in[1];
    const int*   lmk    = (const int*)d_in[2];
    float* out = (float*)d_out;

    eml_fused<<<NBLK, 128>>>(pred, target, lmk, out);
}

// round 4
// speedup vs baseline: 1.0756x; 1.0756x over previous
#include <cuda_runtime.h>
#include <math.h>

// EyesMouthLoss: mean(|pred-target| * (1 + priority*299))
// priority = clip(eye + mouth, 0, 1); region = max_j clip(1 - dist_j/15, 0, 1)
//
// Algebra:  max_j clip(1 - d_j/R) == clip(1 - sqrt(min_j d_j^2)/R)   (2 sqrts/px)
// Pruning:  landmark only touches rows with (y-cy)^2 < R^2 (~85% of rows have none)
// Fused single kernel, O(1) tail: per-block double RED into g_acc + ticket;
// last block writes out and resets accumulators (graph-replay safe).

#define H 512
#define W 512
#define C 3
#define B 16
#define G 2                        // rows per block
#define THREADS 256
#define NBLK2 (B * H / G)          // 4096
#define RADIUS2 225.0f
#define INV_R (1.0f / 15.0f)
#define N_TOTAL ((double)B * C * H * W)

__device__ double g_acc;           // zero-init at load; last block resets each replay
__device__ unsigned int g_count;

__global__ void __launch_bounds__(THREADS) eml_fused(
    const float* __restrict__ pred,
    const float* __restrict__ target,
    const int*   __restrict__ lm,
    float* __restrict__ out)
{
    const int row0 = blockIdx.x * G;       // G rows, same batch (512 % G == 0)
    const int b    = row0 >> 9;
    const int yb   = row0 & (H - 1);
    const int tid  = threadIdx.x;
    const int r    = tid >> 7;             // 0..G-1: which row this thread works
    const int it   = tid & 127;            // 0..127 within row

    __shared__ float s_ecx[G][12], s_ed2[G][12];
    __shared__ float s_mcx[G][20], s_md2[G][20];
    __shared__ int   s_ne[G], s_nm[G];
    __shared__ float s_part[THREADS / 32];
    __shared__ bool  s_last;

    if (tid < G) { s_ne[tid] = 0; s_nm[tid] = 0; }
    __syncthreads();

    // prescan: G*32 threads, one (row, landmark) pair each; keep row-active ones
    if (tid < G * 32) {
        const int pr = tid >> 5;                 // row index within block
        const int li = 36 + (tid & 31);          // landmark 36..67
        const int lx = lm[b * 136 + li * 2 + 0];
        const int ly = lm[b * 136 + li * 2 + 1];
        const float cx = fminf(fmaxf((float)lx, 0.0f), (float)(W - 1));
        const float cy = fminf(fmaxf((float)ly, 0.0f), (float)(H - 1));
        const float dy  = (float)(yb + pr) - cy;
        const float dy2 = dy * dy;
        if (dy2 < RADIUS2) {
            if (li < 48) { int k = atomicAdd(&s_ne[pr], 1); s_ecx[pr][k] = cx; s_ed2[pr][k] = dy2; }
            else         { int k = atomicAdd(&s_nm[pr], 1); s_mcx[pr][k] = cx; s_md2[pr][k] = dy2; }
        }
    }
    __syncthreads();

    const int ne = s_ne[r];
    const int nm = s_nm[r];
    const int y  = yb + r;
    const int x0 = it << 2;

    // weights for this thread's 4 pixels
    float wgt[4];
#pragma unroll
    for (int k = 0; k < 4; k++) wgt[k] = 1.0f;

    if ((ne | nm) != 0) {
#pragma unroll
        for (int k = 0; k < 4; k++) {
            const float xf = (float)(x0 + k);
            float emn = 3.0e8f, mmn = 3.0e8f;
            for (int j = 0; j < ne; j++) {
                const float dx = xf - s_ecx[r][j];
                emn = fminf(emn, fmaf(dx, dx, s_ed2[r][j]));
            }
            for (int j = 0; j < nm; j++) {
                const float dx = xf - s_mcx[r][j];
                mmn = fminf(mmn, fmaf(dx, dx, s_md2[r][j]));
            }
            const float e = (emn < RADIUS2) ? (1.0f - sqrtf(emn) * INV_R) : 0.0f;
            const float m = (mmn < RADIUS2) ? (1.0f - sqrtf(mmn) * INV_R) : 0.0f;
            const float p = fminf(e + m, 1.0f);
            wgt[k] = fmaf(p, 299.0f, 1.0f);
        }
    }

    const size_t rowbase = (size_t)b * (C * H * W) + (size_t)y * W + x0;
    float acc = 0.0f;
#pragma unroll
    for (int c = 0; c < C; c++) {
        const size_t off = rowbase + (size_t)c * (H * W);
        const float4 pv = *reinterpret_cast<const float4*>(pred + off);
        const float4 tv = *reinterpret_cast<const float4*>(target + off);
        acc = fmaf(fabsf(pv.x - tv.x), wgt[0], acc);
        acc = fmaf(fabsf(pv.y - tv.y), wgt[1], acc);
        acc = fmaf(fabsf(pv.z - tv.z), wgt[2], acc);
        acc = fmaf(fabsf(pv.w - tv.w), wgt[3], acc);
    }

    // block reduce (fp32; block sum ~4e3, safe)
#pragma unroll
    for (int s = 16; s > 0; s >>= 1)
        acc += __shfl_xor_sync(0xFFFFFFFFu, acc, s);
    if ((tid & 31) == 0) s_part[tid >> 5] = acc;
    __syncthreads();

    if (tid == 0) {
        float bs = 0.0f;
#pragma unroll
        for (int wsl = 0; wsl < THREADS / 32; wsl++) bs += s_part[wsl];
        atomicAdd(&g_acc, (double)bs);     // relaxed RED, O(1) per block
        __threadfence();                   // release before ticket
        const unsigned int ticket = atomicAdd(&g_count, 1u);
        s_last = (ticket == (unsigned int)(NBLK2 - 1));
    }
    __syncthreads();

    if (s_last && tid == 0) {
        __threadfence();                   // acquire: all REDs visible
        const double total = *((volatile double*)&g_acc);
        out[0] = (float)(total / N_TOTAL);
        g_acc = 0.0;                       // reset for next graph replay
        g_count = 0u;
    }
}

extern "C" void kernel_launch(void* const* d_in, const int* in_sizes, int n_in,
                              void* d_out, int out_size)
{
    const float* pred   = (const float*)d_in[0];
    const float* target = (const float*)d_in[1];
    const int*   lmk    = (const int*)d_in[2];
    float* out = (float*)d_out;

    eml_fused<<<NBLK2, THREADS>>>(pred, target, lmk, out);
}

// round 6
// speedup vs baseline: 1.3089x; 1.2170x over previous
#include <cuda_runtime.h>
#include <math.h>

// EyesMouthLoss: mean(|pred-target| * (1 + priority*299))
// priority = clip(eye + mouth, 0, 1); region = max_j clip(1 - dist_j/15, 0, 1)
//
// Algebra:  max_j clip(1 - d_j/R) == clip(1 - sqrt(min_j d_j^2)/R)   (2 sqrts/px)
// Pruning:  landmark only touches rows with (y-cy)^2 < R^2 (~85% rows have none)
// Tail:     pre-scaled fire-and-forget float RED per block into out[0]
//           (no fence, no ticket, no L1 flush); out zeroed by an async memset
//           graph node.
// Ordering: all 6 float4 loads issued BEFORE the landmark prescan/barrier so
//           the per-block serial preamble hides under DRAM latency.

#define H 512
#define W 512
#define C 3
#define B 16
#define NBLK (B * H)               // 8192
#define RADIUS2 225.0f
#define INV_R (1.0f / 15.0f)
#define INV_N (1.0f / (16.0f * 3.0f * 512.0f * 512.0f))

__global__ void __launch_bounds__(128) eml_main(
    const float* __restrict__ pred,
    const float* __restrict__ target,
    const int*   __restrict__ lm,
    float* __restrict__ out)
{
    // one block per (batch, row)
    const int row = blockIdx.x;            // b*H + y
    const int b   = row >> 9;
    const int y   = row & (H - 1);
    const int tid = threadIdx.x;
    const int x0  = tid << 2;

    // ---- issue all pixel loads first (hide prescan under DRAM latency) ----
    const size_t rowbase = (size_t)b * (C * H * W) + (size_t)y * W + x0;
    const float4 pv0 = *reinterpret_cast<const float4*>(pred   + rowbase);
    const float4 tv0 = *reinterpret_cast<const float4*>(target + rowbase);
    const float4 pv1 = *reinterpret_cast<const float4*>(pred   + rowbase + (size_t)(H * W));
    const float4 tv1 = *reinterpret_cast<const float4*>(target + rowbase + (size_t)(H * W));
    const float4 pv2 = *reinterpret_cast<const float4*>(pred   + rowbase + (size_t)(2 * H * W));
    const float4 tv2 = *reinterpret_cast<const float4*>(target + rowbase + (size_t)(2 * H * W));

    // ---- landmark prescan (row-active only) ----
    __shared__ float s_ecx[12], s_ed2[12];
    __shared__ float s_mcx[20], s_md2[20];
    __shared__ int   s_ne, s_nm;
    __shared__ float s_part[4];

    if (tid == 0) { s_ne = 0; s_nm = 0; }
    __syncthreads();

    if (tid >= 36 && tid < 68) {
        const int lx = lm[b * 136 + tid * 2 + 0];
        const int ly = lm[b * 136 + tid * 2 + 1];
        const float cx = fminf(fmaxf((float)lx, 0.0f), (float)(W - 1));
        const float cy = fminf(fmaxf((float)ly, 0.0f), (float)(H - 1));
        const float dy  = (float)y - cy;
        const float dy2 = dy * dy;
        if (dy2 < RADIUS2) {
            if (tid < 48) { int k = atomicAdd(&s_ne, 1); s_ecx[k] = cx; s_ed2[k] = dy2; }
            else          { int k = atomicAdd(&s_nm, 1); s_mcx[k] = cx; s_md2[k] = dy2; }
        }
    }
    __syncthreads();

    const int ne = s_ne;
    const int nm = s_nm;

    // ---- weights for this thread's 4 pixels ----
    float wgt[4];
#pragma unroll
    for (int k = 0; k < 4; k++) wgt[k] = 1.0f;

    if ((ne | nm) != 0) {
#pragma unroll
        for (int k = 0; k < 4; k++) {
            const float xf = (float)(x0 + k);
            float emn = 3.0e8f, mmn = 3.0e8f;
            for (int j = 0; j < ne; j++) {
                const float dx = xf - s_ecx[j];
                emn = fminf(emn, fmaf(dx, dx, s_ed2[j]));
            }
            for (int j = 0; j < nm; j++) {
                const float dx = xf - s_mcx[j];
                mmn = fminf(mmn, fmaf(dx, dx, s_md2[j]));
            }
            const float e = (emn < RADIUS2) ? (1.0f - sqrtf(emn) * INV_R) : 0.0f;
            const float m = (mmn < RADIUS2) ? (1.0f - sqrtf(mmn) * INV_R) : 0.0f;
            const float p = fminf(e + m, 1.0f);
            wgt[k] = fmaf(p, 299.0f, 1.0f);
        }
    }

    // ---- consume loads ----
    float acc = 0.0f;
    acc = fmaf(fabsf(pv0.x - tv0.x), wgt[0], acc);
    acc = fmaf(fabsf(pv0.y - tv0.y), wgt[1], acc);
    acc = fmaf(fabsf(pv0.z - tv0.z), wgt[2], acc);
    acc = fmaf(fabsf(pv0.w - tv0.w), wgt[3], acc);
    acc = fmaf(fabsf(pv1.x - tv1.x), wgt[0], acc);
    acc = fmaf(fabsf(pv1.y - tv1.y), wgt[1], acc);
    acc = fmaf(fabsf(pv1.z - tv1.z), wgt[2], acc);
    acc = fmaf(fabsf(pv1.w - tv1.w), wgt[3], acc);
    acc = fmaf(fabsf(pv2.x - tv2.x), wgt[0], acc);
    acc = fmaf(fabsf(pv2.y - tv2.y), wgt[1], acc);
    acc = fmaf(fabsf(pv2.z - tv2.z), wgt[2], acc);
    acc = fmaf(fabsf(pv2.w - tv2.w), wgt[3], acc);

    // ---- block reduce ----
#pragma unroll
    for (int s = 16; s > 0; s >>= 1)
        acc += __shfl_xor_sync(0xFFFFFFFFu, acc, s);
    if ((tid & 31) == 0) s_part[tid >> 5] = acc;
    __syncthreads();

    if (tid == 0) {
        const float bs = s_part[0] + s_part[1] + s_part[2] + s_part[3];
        atomicAdd(out, bs * INV_N);   // fire-and-forget REDG, no fence/ticket
    }
}

extern "C" void kernel_launch(void* const* d_in, const int* in_sizes, int n_in,
                              void* d_out, int out_size)
{
    const float* pred   = (const float*)d_in[0];
    const float* target = (const float*)d_in[1];
    const int*   lmk    = (const int*)d_in[2];
    float* out = (float*)d_out;

    cudaMemsetAsync(out, 0, sizeof(float), 0);   // memset node, graph-capturable
    eml_main<<<NBLK, 128>>>(pred, target, lmk, out);
}

// round 7
// speedup vs baseline: 1.4190x; 1.0841x over previous
#include <cuda_runtime.h>
#include <math.h>

// EyesMouthLoss: mean(|pred-target| * (1 + priority*299))
// priority = clip(eye + mouth, 0, 1); region = max_j clip(1 - dist_j/15, 0, 1)
//
// Algebra:  max_j clip(1 - d_j/R) == clip(1 - sqrt(min_j d_j^2)/R)   (2 sqrts/px)
// Pruning:  landmark only touches rows with (y-cy)^2 < R^2 (~85% rows have none)
// Structure (R1 body, best measured): weights FIRST (low live regs -> occ ~70%),
//   then tight float4 load+consume loop; cross-warp occupancy hides DRAM latency.
// Tail (R6, best measured): pre-scaled fire-and-forget f32 REDG per block into
//   out[0]; out zeroed by an async memset graph node. No fence, no ticket.

#define H 512
#define W 512
#define C 3
#define B 16
#define NBLK (B * H)               // 8192
#define RADIUS2 225.0f
#define INV_R (1.0f / 15.0f)
#define INV_N (1.0f / (16.0f * 3.0f * 512.0f * 512.0f))

__global__ void __launch_bounds__(128) eml_main(
    const float* __restrict__ pred,
    const float* __restrict__ target,
    const int*   __restrict__ lm,
    float* __restrict__ out)
{
    // one block per (batch, row)
    const int row = blockIdx.x;            // b*H + y
    const int b   = row >> 9;
    const int y   = row & (H - 1);
    const int tid = threadIdx.x;

    __shared__ float s_ecx[12], s_ed2[12];
    __shared__ float s_mcx[20], s_md2[20];
    __shared__ int   s_ne, s_nm;
    __shared__ float s_part[4];

    if (tid == 0) { s_ne = 0; s_nm = 0; }
    __syncthreads();

    // prescan: threads 36..67 each own one landmark; keep row-active ones
    if (tid >= 36 && tid < 68) {
        const int lx = lm[b * 136 + tid * 2 + 0];
        const int ly = lm[b * 136 + tid * 2 + 1];
        const float cx = fminf(fmaxf((float)lx, 0.0f), (float)(W - 1));
        const float cy = fminf(fmaxf((float)ly, 0.0f), (float)(H - 1));
        const float dy  = (float)y - cy;
        const float dy2 = dy * dy;
        if (dy2 < RADIUS2) {
            if (tid < 48) { int k = atomicAdd(&s_ne, 1); s_ecx[k] = cx; s_ed2[k] = dy2; }
            else          { int k = atomicAdd(&s_nm, 1); s_mcx[k] = cx; s_md2[k] = dy2; }
        }
    }
    __syncthreads();

    const int ne = s_ne;
    const int nm = s_nm;
    const int x0 = tid << 2;

    // ---- weights for this thread's 4 pixels (computed before loads) ----
    float wgt[4];
#pragma unroll
    for (int k = 0; k < 4; k++) wgt[k] = 1.0f;

    if ((ne | nm) != 0) {
#pragma unroll
        for (int k = 0; k < 4; k++) {
            const float xf = (float)(x0 + k);
            float emn = 3.0e8f, mmn = 3.0e8f;
            for (int j = 0; j < ne; j++) {
                const float dx = xf - s_ecx[j];
                emn = fminf(emn, fmaf(dx, dx, s_ed2[j]));
            }
            for (int j = 0; j < nm; j++) {
                const float dx = xf - s_mcx[j];
                mmn = fminf(mmn, fmaf(dx, dx, s_md2[j]));
            }
            const float e = (emn < RADIUS2) ? (1.0f - sqrtf(emn) * INV_R) : 0.0f;
            const float m = (mmn < RADIUS2) ? (1.0f - sqrtf(mmn) * INV_R) : 0.0f;
            const float p = fminf(e + m, 1.0f);
            wgt[k] = fmaf(p, 299.0f, 1.0f);
        }
    }

    // ---- tight load+consume loop (low live regs -> high occupancy) ----
    const size_t rowbase = (size_t)b * (C * H * W) + (size_t)y * W + x0;
    float acc = 0.0f;
#pragma unroll
    for (int c = 0; c < C; c++) {
        const size_t off = rowbase + (size_t)c * (H * W);
        const float4 pv = *reinterpret_cast<const float4*>(pred + off);
        const float4 tv = *reinterpret_cast<const float4*>(target + off);
        acc = fmaf(fabsf(pv.x - tv.x), wgt[0], acc);
        acc = fmaf(fabsf(pv.y - tv.y), wgt[1], acc);
        acc = fmaf(fabsf(pv.z - tv.z), wgt[2], acc);
        acc = fmaf(fabsf(pv.w - tv.w), wgt[3], acc);
    }

    // ---- block reduce ----
#pragma unroll
    for (int s = 16; s > 0; s >>= 1)
        acc += __shfl_xor_sync(0xFFFFFFFFu, acc, s);
    if ((tid & 31) == 0) s_part[tid >> 5] = acc;
    __syncthreads();

    if (tid == 0) {
        const float bs = s_part[0] + s_part[1] + s_part[2] + s_part[3];
        atomicAdd(out, bs * INV_N);   // fire-and-forget REDG, no fence/ticket
    }
}

extern "C" void kernel_launch(void* const* d_in, const int* in_sizes, int n_in,
                              void* d_out, int out_size)
{
    const float* pred   = (const float*)d_in[0];
    const float* target = (const float*)d_in[1];
    const int*   lmk    = (const int*)d_in[2];
    float* out = (float*)d_out;

    cudaMemsetAsync(out, 0, sizeof(float), 0);   // memset node, graph-capturable
    eml_main<<<NBLK, 128>>>(pred, target, lmk, out);
}